// round 10
// baseline (speedup 1.0000x reference)
#include <cuda_runtime.h>
#include <cuda_fp16.h>
#include <cstdint>

// ---------------------------------------------------------------------------
// GCN, 4 layers + heads. R10:
//  - fp16 activations + fp16 agg output; fp32 accumulate; fp16 MMA m16n8k16
//  - agg: lane=uint4, 2 edges per load instruction, shfl_xor(16) combine
//  - W0-2 pre-converted to fp16 transposed [n][k] (parallel, in k_prep grid)
//  - layer-2 GEMM computes z/z2 in-epilogue
//  - k_norm merged into k_fill (parallel+parallel; 1-block scan stays pure)
// ---------------------------------------------------------------------------

constexpr int NN = 50000;
constexpr int NE = 800000;

__device__ int    g_outdeg[NN];
__device__ int    g_indeg[NN];
__device__ float  g_nsrc[NN];
__device__ float  g_ndst[NN];
__device__ int    g_rowptr[NN + 1];
__device__ int    g_cursor[NN];
__device__ int    g_esrc[NE];
__device__ uint4  g_hs[(size_t)NN * 16];    // fp16 activations: 16 uint4 = 128 halves/node
__device__ uint4  g_agg[(size_t)NN * 16];   // fp16 aggregated * norm_dst (GEMM A)
__device__ __half g_whT[3][128 * 128];      // W0..W2 fp16, transposed [n][k]
__device__ float2 g_zz[NN];                 // (z, z2) per node
__device__ float  g_q[128];                 // W3 @ Wp
__device__ float  g_q2[128];                // W3 @ Wv
__device__ float  g_cPI;

__device__ __forceinline__ void mma_f16(float* c, const uint32_t* a,
                                        uint32_t b0, uint32_t b1) {
    asm("mma.sync.aligned.m16n8k16.row.col.f32.f16.f16.f32 "
        "{%0,%1,%2,%3},{%4,%5,%6,%7},{%8,%9},{%0,%1,%2,%3};"
        : "+f"(c[0]), "+f"(c[1]), "+f"(c[2]), "+f"(c[3])
        : "r"(a[0]), "r"(a[1]), "r"(a[2]), "r"(a[3]), "r"(b0), "r"(b1));
}

__device__ __forceinline__ uint2 pack4h(float4 v) {
    uint2 r;
    __half2 h0 = __floats2half2_rn(v.x, v.y);
    __half2 h1 = __floats2half2_rn(v.z, v.w);
    r.x = *(uint32_t*)&h0;
    r.y = *(uint32_t*)&h1;
    return r;
}
__device__ __forceinline__ void unpack8h(uint4 u, float4& lo, float4& hi) {
    __half2 h0 = *(__half2*)&u.x;
    __half2 h1 = *(__half2*)&u.y;
    __half2 h2 = *(__half2*)&u.z;
    __half2 h3 = *(__half2*)&u.w;
    float2 f0 = __half22float2(h0), f1 = __half22float2(h1);
    float2 f2 = __half22float2(h2), f3 = __half22float2(h3);
    lo = make_float4(f0.x, f0.y, f1.x, f1.y);
    hi = make_float4(f2.x, f2.y, f3.x, f3.y);
}

// --------------------------- setup ----------------------------------------

__global__ void k_zero() {
    int i = blockIdx.x * blockDim.x + threadIdx.x;
    if (i < NN) { g_outdeg[i] = 0; g_indeg[i] = 0; }
}

__global__ void k_hist(const int* __restrict__ src, const int* __restrict__ dst) {
    int e = blockIdx.x * blockDim.x + threadIdx.x;
    if (e < NE) {
        atomicAdd(&g_outdeg[src[e]], 1);
        atomicAdd(&g_indeg[dst[e]], 1);
    }
}

// Single-block scan only (no extra parallel work in here — R5/R6 lesson).
__global__ void k_scan() {
    constexpr int CH = (NN + 1023) / 1024;   // 49
    __shared__ int ts[1024];
    int t = threadIdx.x;
    int base = t * CH;
    int s = 0;
    for (int i = 0; i < CH; i++) {
        int idx = base + i;
        int v = (idx < NN) ? g_indeg[idx] : 0;
        if (idx < NN) g_rowptr[idx] = s;
        s += v;
    }
    ts[t] = s;
    __syncthreads();
    for (int off = 1; off < 1024; off <<= 1) {
        int v = (t >= off) ? ts[t - off] : 0;
        __syncthreads();
        ts[t] += v;
        __syncthreads();
    }
    int offset = ts[t] - s;
    for (int i = 0; i < CH; i++) {
        int idx = base + i;
        if (idx < NN) {
            int p = g_rowptr[idx] + offset;
            g_rowptr[idx] = p;
            g_cursor[idx] = p;
        }
    }
    if (t == 1023) g_rowptr[NN] = ts[1023];
}

// CSR fill + norm computation (disjoint parallel ranges)
__global__ void k_fillnorm(const int* __restrict__ src, const int* __restrict__ dst) {
    int i = blockIdx.x * blockDim.x + threadIdx.x;
    if (i < NE) {
        int p = atomicAdd(&g_cursor[dst[i]], 1);
        g_esrc[p] = src[i];
    } else {
        int j = i - NE;
        if (j < NN) {
            g_nsrc[j] = rsqrtf((float)max(g_outdeg[j], 1));
            g_ndst[j] = rsqrtf((float)max(g_indeg[j], 1));
        }
    }
}

// features * nsrc -> fp16 hs (uint4 units: 8 feats/thread)
__global__ void k_scale0(const float* __restrict__ feats) {
    int i = blockIdx.x * blockDim.x + threadIdx.x;   // uint4 index
    constexpr int TOT = NN * 16;
    if (i < TOT) {
        int node = i >> 4;
        float s = g_nsrc[node];
        float4 x0 = ((const float4*)feats)[i * 2];
        float4 x1 = ((const float4*)feats)[i * 2 + 1];
        x0.x *= s; x0.y *= s; x0.z *= s; x0.w *= s;
        x1.x *= s; x1.y *= s; x1.z *= s; x1.w *= s;
        uint2 lo = pack4h(x0), hi = pack4h(x1);
        g_hs[i] = make_uint4(lo.x, lo.y, hi.x, hi.y);
    }
}

// Block 0: head precompute. Blocks 1..192: convert W0-2 to fp16 transposed.
__global__ void k_prep(const float* __restrict__ W0, const float* __restrict__ W1,
                       const float* __restrict__ W2,
                       const float* __restrict__ W3, const float* __restrict__ b3,
                       const float* __restrict__ Wp, const float* __restrict__ bp,
                       const float* __restrict__ Wv, const float* __restrict__ bv,
                       float* __restrict__ out) {
    if (blockIdx.x == 0) {
        int k = threadIdx.x;   // 256 threads; use first 128
        if (k < 128) {
            float a = 0.f, c = 0.f;
            for (int j = 0; j < 64; j++) {
                float w = W3[k * 64 + j];
                a += w * Wp[j];
                c += w * Wv[j];
            }
            g_q[k] = a;
            g_q2[k] = c;
            if (k == 0) {
                float cp = 0.f, cv = 0.f;
                for (int j = 0; j < 64; j++) { cp += b3[j] * Wp[j]; cv += b3[j] * Wv[j]; }
                g_cPI = cp + bp[0];
                out[NN] = (float)NN * cv + bv[0];
            }
        }
    } else {
        int idx = (blockIdx.x - 1) * 256 + threadIdx.x;   // 0 .. 3*16384-1
        if (idx < 3 * 16384) {
            int layer = idx >> 14;
            int rem = idx & 16383;
            int k = rem >> 7;          // coalesced reads along n
            int n = rem & 127;
            const float* W = (layer == 0) ? W0 : (layer == 1) ? W1 : W2;
            g_whT[layer][n * 128 + k] = __float2half(W[k * 128 + n]);
        }
    }
}

// --------------------------- aggregation ----------------------------------
// One warp per node. Lane owns uint4 (8 feats); half-warps split even/odd
// edges -> 2 edges per load instruction. Final shfl_xor(16) combine.

__global__ void k_agg() {
    int v = blockIdx.x * (blockDim.x >> 5) + (threadIdx.x >> 5);
    if (v >= NN) return;
    int lane = threadIdx.x & 31;
    int half = lane >> 4;          // 0: even edges, 1: odd edges
    int l16  = lane & 15;          // feature block (8 feats)
    int beg = g_rowptr[v], end = g_rowptr[v + 1];

    float4 a0l = make_float4(0.f, 0.f, 0.f, 0.f), a0h = a0l;
    float4 a1l = a0l, a1h = a0l;

    int base = beg;
    for (; base + 8 <= end; base += 8) {
        int u0 = g_esrc[base + half];
        int u1 = g_esrc[base + 2 + half];
        int u2 = g_esrc[base + 4 + half];
        int u3 = g_esrc[base + 6 + half];
        uint4 x0 = g_hs[(size_t)u0 * 16 + l16];
        uint4 x1 = g_hs[(size_t)u1 * 16 + l16];
        uint4 x2 = g_hs[(size_t)u2 * 16 + l16];
        uint4 x3 = g_hs[(size_t)u3 * 16 + l16];
        float4 lo, hi;
        unpack8h(x0, lo, hi);
        a0l.x += lo.x; a0l.y += lo.y; a0l.z += lo.z; a0l.w += lo.w;
        a0h.x += hi.x; a0h.y += hi.y; a0h.z += hi.z; a0h.w += hi.w;
        unpack8h(x1, lo, hi);
        a1l.x += lo.x; a1l.y += lo.y; a1l.z += lo.z; a1l.w += lo.w;
        a1h.x += hi.x; a1h.y += hi.y; a1h.z += hi.z; a1h.w += hi.w;
        unpack8h(x2, lo, hi);
        a0l.x += lo.x; a0l.y += lo.y; a0l.z += lo.z; a0l.w += lo.w;
        a0h.x += hi.x; a0h.y += hi.y; a0h.z += hi.z; a0h.w += hi.w;
        unpack8h(x3, lo, hi);
        a1l.x += lo.x; a1l.y += lo.y; a1l.z += lo.z; a1l.w += lo.w;
        a1h.x += hi.x; a1h.y += hi.y; a1h.z += hi.z; a1h.w += hi.w;
    }
    for (int e = base + half; e < end; e += 2) {
        uint4 x = g_hs[(size_t)g_esrc[e] * 16 + l16];
        float4 lo, hi;
        unpack8h(x, lo, hi);
        a0l.x += lo.x; a0l.y += lo.y; a0l.z += lo.z; a0l.w += lo.w;
        a0h.x += hi.x; a0h.y += hi.y; a0h.z += hi.z; a0h.w += hi.w;
    }

    float s[8];
    s[0] = a0l.x + a1l.x; s[1] = a0l.y + a1l.y;
    s[2] = a0l.z + a1l.z; s[3] = a0l.w + a1l.w;
    s[4] = a0h.x + a1h.x; s[5] = a0h.y + a1h.y;
    s[6] = a0h.z + a1h.z; s[7] = a0h.w + a1h.w;
    #pragma unroll
    for (int j = 0; j < 8; j++)
        s[j] += __shfl_xor_sync(0xffffffff, s[j], 16);

    if (half == 0) {
        float nd = g_ndst[v];
        uint2 lo = pack4h(make_float4(s[0] * nd, s[1] * nd, s[2] * nd, s[3] * nd));
        uint2 hi = pack4h(make_float4(s[4] * nd, s[5] * nd, s[6] * nd, s[7] * nd));
        g_agg[(size_t)v * 16 + l16] = make_uint4(lo.x, lo.y, hi.x, hi.y);
    }
}

// --------------------------- fp16 tensor-core GEMM -------------------------
// out = relu(g_agg @ W + b) * nsrc; W pre-staged fp16 transposed [n][k].
// Block: 128 rows x 128 cols, 256 threads, mma m16n8k16.

constexpr int PADH = 136;                          // halves
constexpr int GEMM_SMEM = 2 * 128 * PADH * 2;      // 69632 B

template <bool TAIL>
__global__ void __launch_bounds__(256) k_gemm(int layer,
                                              const float* __restrict__ bia) {
    extern __shared__ __half smh[];
    __half* sA = smh;                    // [row][k]
    __half* sW = smh + 128 * PADH;       // [n][k]

    int tid  = threadIdx.x;
    int lane = tid & 31;
    int warp = tid >> 5;
    int row0 = blockIdx.x * 128;

    // stage A: copy fp16 rows (2048 uint4)
    #pragma unroll
    for (int it = 0; it < 8; it++) {
        int i = it * 256 + tid;
        int r = i >> 4, c = i & 15;
        int gr = row0 + r;
        uint4 v = (gr < NN) ? g_agg[(size_t)gr * 16 + c]
                            : make_uint4(0u, 0u, 0u, 0u);
        *(uint4*)&sA[r * PADH + c * 8] = v;
    }
    // stage W: pure fp16 copy (2048 uint4), already transposed
    const uint4* WT4 = (const uint4*)g_whT[layer];
    #pragma unroll
    for (int it = 0; it < 8; it++) {
        int i = it * 256 + tid;
        int n = i >> 4, c = i & 15;
        *(uint4*)&sW[n * PADH + c * 8] = WT4[n * 16 + c];
    }
    __syncthreads();

    int wm = (warp >> 1) * 32;           // warp row offset
    int wn = (warp & 1) * 64;            // warp col offset
    int qr = lane >> 2;                  // 0..7
    int qc = lane & 3;                   // 0..3

    float acc[2][8][4];
    #pragma unroll
    for (int mf = 0; mf < 2; mf++)
        #pragma unroll
        for (int nf = 0; nf < 8; nf++)
            #pragma unroll
            for (int j = 0; j < 4; j++) acc[mf][nf][j] = 0.f;

    #pragma unroll
    for (int ks = 0; ks < 8; ks++) {
        int kb = ks * 16;
        uint32_t a[2][4];
        #pragma unroll
        for (int mf = 0; mf < 2; mf++) {
            int r = wm + mf * 16 + qr;
            a[mf][0] = *(const uint32_t*)&sA[r * PADH + kb + qc * 2];
            a[mf][1] = *(const uint32_t*)&sA[(r + 8) * PADH + kb + qc * 2];
            a[mf][2] = *(const uint32_t*)&sA[r * PADH + kb + 8 + qc * 2];
            a[mf][3] = *(const uint32_t*)&sA[(r + 8) * PADH + kb + 8 + qc * 2];
        }
        #pragma unroll
        for (int nf = 0; nf < 8; nf++) {
            int n = wn + nf * 8 + qr;
            uint32_t b0 = *(const uint32_t*)&sW[n * PADH + kb + qc * 2];
            uint32_t b1 = *(const uint32_t*)&sW[n * PADH + kb + 8 + qc * 2];
            mma_f16(acc[0][nf], a[0], b0, b1);
            mma_f16(acc[1][nf], a[1], b0, b1);
        }
    }

    if (!TAIL) {
        #pragma unroll
        for (int mf = 0; mf < 2; mf++) {
            int r0 = row0 + wm + mf * 16 + qr;
            int r1 = r0 + 8;
            float s0 = (r0 < NN) ? g_nsrc[r0] : 0.f;
            float s1 = (r1 < NN) ? g_nsrc[r1] : 0.f;
            #pragma unroll
            for (int nf = 0; nf < 8; nf++) {
                int c = wn + nf * 8 + qc * 2;
                float2 bb = *(const float2*)&bia[c];
                if (r0 < NN) {
                    __half2 h = __floats2half2_rn(
                        fmaxf(acc[mf][nf][0] + bb.x, 0.f) * s0,
                        fmaxf(acc[mf][nf][1] + bb.y, 0.f) * s0);
                    ((__half2*)g_hs)[(size_t)r0 * 64 + (c >> 1)] = h;
                }
                if (r1 < NN) {
                    __half2 h = __floats2half2_rn(
                        fmaxf(acc[mf][nf][2] + bb.x, 0.f) * s1,
                        fmaxf(acc[mf][nf][3] + bb.y, 0.f) * s1);
                    ((__half2*)g_hs)[(size_t)r1 * 64 + (c >> 1)] = h;
                }
            }
        }
    } else {
        float* zred = (float*)smh;
        __syncthreads();
        if (tid < 256) zred[tid] = 0.f;
        __syncthreads();
        #pragma unroll
        for (int mf = 0; mf < 2; mf++) {
            int rl0 = wm + mf * 16 + qr;
            int rl1 = rl0 + 8;
            int r0 = row0 + rl0, r1 = row0 + rl1;
            float s0 = (r0 < NN) ? g_nsrc[r0] : 0.f;
            float s1 = (r1 < NN) ? g_nsrc[r1] : 0.f;
            float zl0 = 0.f, z2l0 = 0.f, zl1 = 0.f, z2l1 = 0.f;
            #pragma unroll
            for (int nf = 0; nf < 8; nf++) {
                int c = wn + nf * 8 + qc * 2;
                float2 bb  = *(const float2*)&bia[c];
                float2 qv  = *(const float2*)&g_q[c];
                float2 qv2 = *(const float2*)&g_q2[c];
                float h00 = fmaxf(acc[mf][nf][0] + bb.x, 0.f) * s0;
                float h01 = fmaxf(acc[mf][nf][1] + bb.y, 0.f) * s0;
                float h10 = fmaxf(acc[mf][nf][2] + bb.x, 0.f) * s1;
                float h11 = fmaxf(acc[mf][nf][3] + bb.y, 0.f) * s1;
                zl0  += h00 * qv.x  + h01 * qv.y;
                z2l0 += h00 * qv2.x + h01 * qv2.y;
                zl1  += h10 * qv.x  + h11 * qv.y;
                z2l1 += h10 * qv2.x + h11 * qv2.y;
            }
            atomicAdd(&zred[rl0 * 2],     zl0);
            atomicAdd(&zred[rl0 * 2 + 1], z2l0);
            atomicAdd(&zred[rl1 * 2],     zl1);
            atomicAdd(&zred[rl1 * 2 + 1], z2l1);
        }
        __syncthreads();
        if (tid < 128 && row0 + tid < NN)
            g_zz[row0 + tid] = make_float2(zred[tid * 2], zred[tid * 2 + 1]);
    }
}

// ---------------------- final edge pass + heads ----------------------------

__global__ void k_zagg(float* __restrict__ out) {
    __shared__ float red[256];
    int v = blockIdx.x * blockDim.x + threadIdx.x;
    float vp = 0.f;
    if (v < NN) {
        int beg = g_rowptr[v], end = g_rowptr[v + 1];
        float s0 = 0.f, s1 = 0.f, t0 = 0.f, t1 = 0.f;
        int e = beg;
        for (; e + 1 < end; e += 2) {
            float2 a = g_zz[g_esrc[e]];
            float2 b = g_zz[g_esrc[e + 1]];
            s0 += a.x; t0 += a.y;
            s1 += b.x; t1 += b.y;
        }
        if (e < end) {
            float2 a = g_zz[g_esrc[e]];
            s0 += a.x; t0 += a.y;
        }
        float nd = g_ndst[v];
        out[v] = nd * (s0 + s1) + g_cPI;
        vp = nd * (t0 + t1);
    }
    red[threadIdx.x] = vp;
    __syncthreads();
    for (int off = 128; off; off >>= 1) {
        if (threadIdx.x < off) red[threadIdx.x] += red[threadIdx.x + off];
        __syncthreads();
    }
    if (threadIdx.x == 0) atomicAdd(&out[NN], red[0]);
}

// --------------------------- launch ----------------------------------------

extern "C" void kernel_launch(void* const* d_in, const int* in_sizes, int n_in,
                              void* d_out, int out_size) {
    const float* feats = (const float*)d_in[0];
    const int*   src   = (const int*)d_in[1];
    const int*   dst   = (const int*)d_in[2];
    const float* W0 = (const float*)d_in[3];  const float* b0 = (const float*)d_in[4];
    const float* W1 = (const float*)d_in[5];  const float* b1 = (const float*)d_in[6];
    const float* W2 = (const float*)d_in[7];  const float* b2 = (const float*)d_in[8];
    const float* W3 = (const float*)d_in[9];  const float* b3 = (const float*)d_in[10];
    const float* Wp = (const float*)d_in[11]; const float* bp = (const float*)d_in[12];
    const float* Wv = (const float*)d_in[13]; const float* bv = (const float*)d_in[14];
    float* out = (float*)d_out;

    cudaFuncSetAttribute(k_gemm<false>, cudaFuncAttributeMaxDynamicSharedMemorySize,
                         GEMM_SMEM);
    cudaFuncSetAttribute(k_gemm<true>, cudaFuncAttributeMaxDynamicSharedMemorySize,
                         GEMM_SMEM);

    k_zero<<<(NN + 255) / 256, 256>>>();
    k_hist<<<(NE + 255) / 256, 256>>>(src, dst);
    k_scan<<<1, 1024>>>();
    k_fillnorm<<<(NE + NN + 255) / 256, 256>>>(src, dst);
    k_prep<<<1 + (3 * 16384 + 255) / 256, 256>>>(W0, W1, W2, W3, b3, Wp, bp, Wv, bv, out);
    k_scale0<<<(NN * 16 + 255) / 256, 256>>>(feats);

    const int aggGrid  = (NN + 7) / 8;        // 8 warps/block
    const int gemmGrid = (NN + 127) / 128;    // 391

    k_agg<<<aggGrid, 256>>>();
    k_gemm<false><<<gemmGrid, 256, GEMM_SMEM>>>(0, b0);
    k_agg<<<aggGrid, 256>>>();
    k_gemm<false><<<gemmGrid, 256, GEMM_SMEM>>>(1, b1);
    k_agg<<<aggGrid, 256>>>();
    k_gemm<true><<<gemmGrid, 256, GEMM_SMEM>>>(2, b2);

    k_zagg<<<(NN + 255) / 256, 256>>>(out);
}